// round 1
// baseline (speedup 1.0000x reference)
#include <cuda_runtime.h>

// JacobianLayer: J[b] = W3^T diag(1-h2^2) W2^T diag(1-h1^2) W1^T
// B=8192, D=64, H=256.
//
// One CTA per SM (grid=148), 256 threads, grid-stride over batch.
// Smem: W1T [256][64], W3 [256][64], Q scratch [256][64]  (~199 KB)
// Stage1 (fused with h2 forward): thread t owns k=t, accumulates
//   Q[k,j] = g2[k] * sum_l W2[l,k] * g1[l] * W1[j,l]   (64 accs, packed f32x2)
// Stage2: thread t owns a 4x4 tile of J:
//   J[i,j] = sum_k W3[k,i] * Q[k,j]

#define BATCH 8192
#define D 64
#define H 256
#define NTHREADS 256
#define NUM_SMS 148

typedef unsigned long long u64t;

__device__ __forceinline__ u64t pack2(float s) {
    u64t r;
    asm("mov.b64 %0, {%1, %1};" : "=l"(r) : "f"(s));
    return r;
}
__device__ __forceinline__ u64t fma2(u64t a, u64t b, u64t c) {
    u64t d;
    asm("fma.rn.f32x2 %0, %1, %2, %3;" : "=l"(d) : "l"(a), "l"(b), "l"(c));
    return d;
}
__device__ __forceinline__ u64t mul2(u64t a, u64t b) {
    u64t d;
    asm("mul.rn.f32x2 %0, %1, %2;" : "=l"(d) : "l"(a), "l"(b));
    return d;
}
__device__ __forceinline__ float2 unpack2(u64t a) {
    float2 f;
    asm("mov.b64 {%0, %1}, %2;" : "=f"(f.x), "=f"(f.y) : "l"(a));
    return f;
}

__global__ void __launch_bounds__(NTHREADS, 1)
jac_kernel(const float* __restrict__ x,  const float* __restrict__ W1,
           const float* __restrict__ b1, const float* __restrict__ W2,
           const float* __restrict__ b2, const float* __restrict__ W3,
           float* __restrict__ out)
{
    extern __shared__ float sm[];
    float* W1Ts = sm;               // [H][D]: W1T[l][j] = W1[j][l]
    float* W3s  = W1Ts + H * D;     // [H][D]: W3[k][i] (native layout)
    float* Qs   = W3s + H * D;      // [H][D]: Q[k][j] (g2-scaled)
    float* h1s  = Qs + H * D;       // [H]
    float* g1s  = h1s + H;          // [H]
    float* xs   = g1s + H;          // [D]

    const int t = threadIdx.x;

    // ---- one-time weight staging ----
    for (int idx = t; idx < D * H; idx += NTHREADS) {
        const int j = idx / H;          // W1 row (input dim)
        const int l = idx - j * H;      // W1 col (hidden)
        W1Ts[l * D + j] = W1[idx];
    }
    for (int idx = t; idx < H * D; idx += NTHREADS)
        W3s[idx] = W3[idx];
    __syncthreads();

    const float b1t = b1[t];
    const float b2t = b2[t];

    for (int b = blockIdx.x; b < BATCH; b += gridDim.x) {
        // ---- load x[b] ----
        if (t < D) xs[t] = x[(size_t)b * D + t];
        __syncthreads();

        // ---- h1 = tanh(x @ W1 + b1), g1 = 1 - h1^2 ----
        {
            float u0 = 0.f, u1 = 0.f, u2 = 0.f, u3 = 0.f;
            #pragma unroll
            for (int d4 = 0; d4 < D; d4 += 4) {
                u0 = fmaf(xs[d4 + 0], W1[(d4 + 0) * H + t], u0);
                u1 = fmaf(xs[d4 + 1], W1[(d4 + 1) * H + t], u1);
                u2 = fmaf(xs[d4 + 2], W1[(d4 + 2) * H + t], u2);
                u3 = fmaf(xs[d4 + 3], W1[(d4 + 3) * H + t], u3);
            }
            const float h = tanhf((u0 + u1) + (u2 + u3) + b1t);
            h1s[t] = h;
            g1s[t] = 1.0f - h * h;
        }
        __syncthreads();

        // ---- fused: h2 pre-activation + Stage1 ----
        // thread t = column k of W2; acc[j-pair] over 64 j's
        u64t acc[32];
        #pragma unroll
        for (int q = 0; q < 32; q++) acc[q] = 0ull;

        float v0 = b2t, v1 = 0.f;   // h2 pre-activation partials

        #pragma unroll 1
        for (int l0 = 0; l0 < H; l0 += 8) {
            float w2v[8];
            #pragma unroll
            for (int u = 0; u < 8; u++)
                w2v[u] = W2[(l0 + u) * H + t];   // coalesced column reads, MLP=8
            #pragma unroll
            for (int u = 0; u < 8; u++) {
                const int l = l0 + u;
                const float w = w2v[u];
                if (u & 1) v1 = fmaf(h1s[l], w, v1);
                else       v0 = fmaf(h1s[l], w, v0);
                const u64t s2 = pack2(g1s[l] * w);    // fold diag(g1)
                const ulonglong2* wrow = (const ulonglong2*)(W1Ts + l * D);
                #pragma unroll
                for (int q = 0; q < 16; q++) {
                    const ulonglong2 wv = wrow[q];     // broadcast LDS.128
                    acc[2 * q]     = fma2(wv.x, s2, acc[2 * q]);
                    acc[2 * q + 1] = fma2(wv.y, s2, acc[2 * q + 1]);
                }
            }
        }

        // g2 for this k, fold into Q writeback
        const float h2v = tanhf(v0 + v1);
        const u64t g2p = pack2(1.0f - h2v * h2v);
        u64t* qrow = (u64t*)(Qs + t * D);
        #pragma unroll
        for (int q = 0; q < 32; q++) qrow[q] = mul2(acc[q], g2p);
        __syncthreads();

        // ---- Stage2: J[i,j] = sum_k W3[k,i] * Q[k,j]; 4x4 tile per thread ----
        const int j0 = (t & 15) * 4;
        const int i0 = (t >> 4) * 4;
        u64t c00 = 0, c01 = 0, c10 = 0, c11 = 0;
        u64t c20 = 0, c21 = 0, c30 = 0, c31 = 0;
        #pragma unroll 4
        for (int k = 0; k < H; k++) {
            const float4 a4 = *(const float4*)(W3s + k * D + i0);
            const ulonglong2 bv = *(const ulonglong2*)(Qs + k * D + j0);
            u64t a;
            a = pack2(a4.x); c00 = fma2(bv.x, a, c00); c01 = fma2(bv.y, a, c01);
            a = pack2(a4.y); c10 = fma2(bv.x, a, c10); c11 = fma2(bv.y, a, c11);
            a = pack2(a4.z); c20 = fma2(bv.x, a, c20); c21 = fma2(bv.y, a, c21);
            a = pack2(a4.w); c30 = fma2(bv.x, a, c30); c31 = fma2(bv.y, a, c31);
        }

        // ---- writeback 4x4 tile ----
        float* op = out + (size_t)b * (D * D);
        {
            float2 lo, hi;
            lo = unpack2(c00); hi = unpack2(c01);
            *(float4*)(op + (i0 + 0) * D + j0) = make_float4(lo.x, lo.y, hi.x, hi.y);
            lo = unpack2(c10); hi = unpack2(c11);
            *(float4*)(op + (i0 + 1) * D + j0) = make_float4(lo.x, lo.y, hi.x, hi.y);
            lo = unpack2(c20); hi = unpack2(c21);
            *(float4*)(op + (i0 + 2) * D + j0) = make_float4(lo.x, lo.y, hi.x, hi.y);
            lo = unpack2(c30); hi = unpack2(c31);
            *(float4*)(op + (i0 + 3) * D + j0) = make_float4(lo.x, lo.y, hi.x, hi.y);
        }
        __syncthreads();   // protect smem reuse for next batch
    }
}

extern "C" void kernel_launch(void* const* d_in, const int* in_sizes, int n_in,
                              void* d_out, int out_size)
{
    const float* x  = (const float*)d_in[0];
    const float* W1 = (const float*)d_in[1];
    const float* b1 = (const float*)d_in[2];
    const float* W2 = (const float*)d_in[3];
    const float* b2 = (const float*)d_in[4];
    const float* W3 = (const float*)d_in[5];
    // d_in[6] = b3: does not affect the Jacobian
    float* out = (float*)d_out;

    const int smem_bytes = (3 * H * D + 2 * H + D) * (int)sizeof(float); // ~199 KB
    cudaFuncSetAttribute(jac_kernel,
                         cudaFuncAttributeMaxDynamicSharedMemorySize, smem_bytes);
    jac_kernel<<<NUM_SMS, NTHREADS, smem_bytes>>>(x, W1, b1, W2, b2, W3, out);
}

// round 2
// speedup vs baseline: 1.0001x; 1.0001x over previous
#include <cuda_runtime.h>

// JacobianLayer: J[b] = W3^T diag(1-h2^2) W2^T diag(1-h1^2) W1^T
// B=8192, D=64, H=256.
//
// One CTA per SM (grid=148), 256 threads, grid-stride over batch.
// Smem: W1T [256][64], W3 [256][64], Q scratch [256][64]  (~199 KB)
// Stage1 (fused with h2 forward): thread t owns k=t, accumulates
//   Q[k,j] = g2[k] * sum_l W2[l,k] * g1[l] * W1[j,l]   (64 accs, packed f32x2)
// Stage2: thread t owns a 4x4 tile of J:
//   J[i,j] = sum_k W3[k,i] * Q[k,j]

#define BATCH 8192
#define D 64
#define H 256
#define NTHREADS 256
#define NUM_SMS 148

typedef unsigned long long u64t;

__device__ __forceinline__ u64t pack2(float s) {
    u64t r;
    asm("mov.b64 %0, {%1, %1};" : "=l"(r) : "f"(s));
    return r;
}
__device__ __forceinline__ u64t fma2(u64t a, u64t b, u64t c) {
    u64t d;
    asm("fma.rn.f32x2 %0, %1, %2, %3;" : "=l"(d) : "l"(a), "l"(b), "l"(c));
    return d;
}
__device__ __forceinline__ u64t mul2(u64t a, u64t b) {
    u64t d;
    asm("mul.rn.f32x2 %0, %1, %2;" : "=l"(d) : "l"(a), "l"(b));
    return d;
}
__device__ __forceinline__ float2 unpack2(u64t a) {
    float2 f;
    asm("mov.b64 {%0, %1}, %2;" : "=f"(f.x), "=f"(f.y) : "l"(a));
    return f;
}

__global__ void __launch_bounds__(NTHREADS, 1)
jac_kernel(const float* __restrict__ x,  const float* __restrict__ W1,
           const float* __restrict__ b1, const float* __restrict__ W2,
           const float* __restrict__ b2, const float* __restrict__ W3,
           float* __restrict__ out)
{
    extern __shared__ float sm[];
    float* W1Ts = sm;               // [H][D]: W1T[l][j] = W1[j][l]
    float* W3s  = W1Ts + H * D;     // [H][D]: W3[k][i] (native layout)
    float* Qs   = W3s + H * D;      // [H][D]: Q[k][j] (g2-scaled)
    float* h1s  = Qs + H * D;       // [H]
    float* g1s  = h1s + H;          // [H]
    float* xs   = g1s + H;          // [D]

    const int t = threadIdx.x;

    // ---- one-time weight staging ----
    for (int idx = t; idx < D * H; idx += NTHREADS) {
        const int j = idx / H;          // W1 row (input dim)
        const int l = idx - j * H;      // W1 col (hidden)
        W1Ts[l * D + j] = W1[idx];
    }
    for (int idx = t; idx < H * D; idx += NTHREADS)
        W3s[idx] = W3[idx];
    __syncthreads();

    const float b1t = b1[t];
    const float b2t = b2[t];

    for (int b = blockIdx.x; b < BATCH; b += gridDim.x) {
        // ---- load x[b] ----
        if (t < D) xs[t] = x[(size_t)b * D + t];
        __syncthreads();

        // ---- h1 = tanh(x @ W1 + b1), g1 = 1 - h1^2 ----
        {
            float u0 = 0.f, u1 = 0.f, u2 = 0.f, u3 = 0.f;
            #pragma unroll
            for (int d4 = 0; d4 < D; d4 += 4) {
                u0 = fmaf(xs[d4 + 0], W1[(d4 + 0) * H + t], u0);
                u1 = fmaf(xs[d4 + 1], W1[(d4 + 1) * H + t], u1);
                u2 = fmaf(xs[d4 + 2], W1[(d4 + 2) * H + t], u2);
                u3 = fmaf(xs[d4 + 3], W1[(d4 + 3) * H + t], u3);
            }
            const float h = tanhf((u0 + u1) + (u2 + u3) + b1t);
            h1s[t] = h;
            g1s[t] = 1.0f - h * h;
        }
        __syncthreads();

        // ---- fused: h2 pre-activation + Stage1 ----
        // thread t = column k of W2; acc[j-pair] over 64 j's
        u64t acc[32];
        #pragma unroll
        for (int q = 0; q < 32; q++) acc[q] = 0ull;

        float v0 = b2t, v1 = 0.f;   // h2 pre-activation partials

        #pragma unroll 1
        for (int l0 = 0; l0 < H; l0 += 8) {
            float w2v[8];
            #pragma unroll
            for (int u = 0; u < 8; u++)
                w2v[u] = W2[(l0 + u) * H + t];   // coalesced column reads, MLP=8
            #pragma unroll
            for (int u = 0; u < 8; u++) {
                const int l = l0 + u;
                const float w = w2v[u];
                if (u & 1) v1 = fmaf(h1s[l], w, v1);
                else       v0 = fmaf(h1s[l], w, v0);
                const u64t s2 = pack2(g1s[l] * w);    // fold diag(g1)
                const ulonglong2* wrow = (const ulonglong2*)(W1Ts + l * D);
                #pragma unroll
                for (int q = 0; q < 16; q++) {
                    const ulonglong2 wv = wrow[q];     // broadcast LDS.128
                    acc[2 * q]     = fma2(wv.x, s2, acc[2 * q]);
                    acc[2 * q + 1] = fma2(wv.y, s2, acc[2 * q + 1]);
                }
            }
        }

        // g2 for this k, fold into Q writeback
        const float h2v = tanhf(v0 + v1);
        const u64t g2p = pack2(1.0f - h2v * h2v);
        u64t* qrow = (u64t*)(Qs + t * D);
        #pragma unroll
        for (int q = 0; q < 32; q++) qrow[q] = mul2(acc[q], g2p);
        __syncthreads();

        // ---- Stage2: J[i,j] = sum_k W3[k,i] * Q[k,j]; 4x4 tile per thread ----
        const int j0 = (t & 15) * 4;
        const int i0 = (t >> 4) * 4;
        u64t c00 = 0, c01 = 0, c10 = 0, c11 = 0;
        u64t c20 = 0, c21 = 0, c30 = 0, c31 = 0;
        #pragma unroll 4
        for (int k = 0; k < H; k++) {
            const float4 a4 = *(const float4*)(W3s + k * D + i0);
            const ulonglong2 bv = *(const ulonglong2*)(Qs + k * D + j0);
            u64t a;
            a = pack2(a4.x); c00 = fma2(bv.x, a, c00); c01 = fma2(bv.y, a, c01);
            a = pack2(a4.y); c10 = fma2(bv.x, a, c10); c11 = fma2(bv.y, a, c11);
            a = pack2(a4.z); c20 = fma2(bv.x, a, c20); c21 = fma2(bv.y, a, c21);
            a = pack2(a4.w); c30 = fma2(bv.x, a, c30); c31 = fma2(bv.y, a, c31);
        }

        // ---- writeback 4x4 tile ----
        float* op = out + (size_t)b * (D * D);
        {
            float2 lo, hi;
            lo = unpack2(c00); hi = unpack2(c01);
            *(float4*)(op + (i0 + 0) * D + j0) = make_float4(lo.x, lo.y, hi.x, hi.y);
            lo = unpack2(c10); hi = unpack2(c11);
            *(float4*)(op + (i0 + 1) * D + j0) = make_float4(lo.x, lo.y, hi.x, hi.y);
            lo = unpack2(c20); hi = unpack2(c21);
            *(float4*)(op + (i0 + 2) * D + j0) = make_float4(lo.x, lo.y, hi.x, hi.y);
            lo = unpack2(c30); hi = unpack2(c31);
            *(float4*)(op + (i0 + 3) * D + j0) = make_float4(lo.x, lo.y, hi.x, hi.y);
        }
        __syncthreads();   // protect smem reuse for next batch
    }
}

extern "C" void kernel_launch(void* const* d_in, const int* in_sizes, int n_in,
                              void* d_out, int out_size)
{
    const float* x  = (const float*)d_in[0];
    const float* W1 = (const float*)d_in[1];
    const float* b1 = (const float*)d_in[2];
    const float* W2 = (const float*)d_in[3];
    const float* b2 = (const float*)d_in[4];
    const float* W3 = (const float*)d_in[5];
    // d_in[6] = b3: does not affect the Jacobian
    float* out = (float*)d_out;

    const int smem_bytes = (3 * H * D + 2 * H + D) * (int)sizeof(float); // ~199 KB
    cudaFuncSetAttribute(jac_kernel,
                         cudaFuncAttributeMaxDynamicSharedMemorySize, smem_bytes);
    jac_kernel<<<NUM_SMS, NTHREADS, smem_bytes>>>(x, W1, b1, W2, b2, W3, out);
}